// round 10
// baseline (speedup 1.0000x reference)
#include <cuda_runtime.h>
#include <cuda_pipeline.h>
#include <math.h>

// Problem dims
#define TT   20
#define NN   50000
#define KK   10000
#define RNN  128
#define EMB  64
#define INS  2
#define OUTD 5
#define G2   16
#define ZDIM 256            // [ie(64) | te(64) | h(128)]
#define GDIM 512            // 4*RNN

// GEMM tiling
#define BR   32             // rows per block
#define BK   16             // k-chunk
#define NCH  (ZDIM / BK)    // 16 chunks
#define GB   ((KK + BR - 1) / BR)   // 313 blocks
#define KPAD (GB * BR)              // 10016

// ---------------- device scratch (static, zero-initialized) ----------------
__device__ float g_A[(size_t)KPAD * ZDIM];     // activation matrix per frame
__device__ float g_sh[(size_t)KK * RNN];       // staged h_new
__device__ float g_sc[(size_t)KK * RNN];       // staged c_new
__device__ float g_so[(size_t)KK * OUTD];      // staged out
__device__ int   g_winner[NN];                 // last-k-wins tag per node

__device__ __forceinline__ float sigm(float x) { return 1.0f / (1.0f + expf(-x)); }

// ---------------- init winner tags ----------------
__global__ void winner_init_kernel() {
    int i = blockIdx.x * blockDim.x + threadIdx.x;
    if (i < NN) g_winner[i] = -1;
}

// ---------------- prep: build A = [relu(x@W_in+b) | relu(obs@W_obs+b) | h gather] ----------------
__global__ void prep_kernel(const float* __restrict__ input_data,   // [T,N,2]
                            const float* __restrict__ grids,        // [T,K,16]
                            const float* __restrict__ hbuf,         // [N,128]
                            const int*   __restrict__ aidx,         // [T,K]
                            const float* __restrict__ W_in,  const float* __restrict__ b_in,
                            const float* __restrict__ W_obs, const float* __restrict__ b_obs,
                            int t) {
    __shared__ float sWin[2 * EMB];
    __shared__ float sBin[EMB];
    __shared__ float sWobs[G2 * EMB];
    __shared__ float sBobs[EMB];
    const int tid = threadIdx.x;
    if (tid < 128) sWin[tid] = W_in[tid];
    if (tid < 64)  sBin[tid] = b_in[tid];
    for (int i = tid; i < G2 * EMB; i += 256) sWobs[i] = W_obs[i];
    if (tid >= 64 && tid < 128) sBobs[tid - 64] = b_obs[tid - 64];
    __syncthreads();

    const float* frame = input_data + (size_t)t * NN * INS;
    const float* obs   = grids      + (size_t)t * KK * G2;
    const int*   idx   = aidx       + (size_t)t * KK;

    const int base = blockIdx.x * 16;
    for (int r = 0; r < 16; r++) {
        const int k = base + r;
        const int id = idx[k];
        float* Arow = g_A + (size_t)k * ZDIM;
        if (tid == 0) atomicMax(&g_winner[id], t * KK + k);
        if (tid < 64) {
            float v = frame[id * 2] * sWin[tid] + frame[id * 2 + 1] * sWin[64 + tid] + sBin[tid];
            Arow[tid] = fmaxf(v, 0.0f);
        } else if (tid < 128) {
            const int j = tid - 64;
            float s = sBobs[j];
            #pragma unroll
            for (int m = 0; m < 16; m++) s += obs[k * 16 + m] * sWobs[m * 64 + j];
            Arow[tid] = fmaxf(s, 0.0f);
        } else {
            Arow[tid] = hbuf[(size_t)id * RNN + (tid - 128)];
        }
    }
}

// ---------------- gates GEMM + LSTM elementwise + output head ----------------
// smem layout (floats):
//  [0 .. 1024)                     sAs (2 x 16 x 32, 512 per buffer)  \ union with sG
//  [1024 .. 17408)                 sBs (2 x 16 x 512)                 /  (sG = 32 x 512 = 16384)
//  [17408 .. 21632)                sH  (32 x 132, padded)
//  [21632 .. 21664)                sIdx (32 ints)
#define SM_FLOATS (17408 + 32 * 132 + 32)
#define SM_BYTES  (SM_FLOATS * 4)

__global__ __launch_bounds__(256, 2)
void gates_kernel(const float* __restrict__ W_ih, const float* __restrict__ W_hh,
                  const float* __restrict__ b_ih, const float* __restrict__ b_hh,
                  const float* __restrict__ W_out, const float* __restrict__ b_out,
                  const float* __restrict__ cbuf,
                  const int*   __restrict__ idx) {
    extern __shared__ float smem[];
    float* sAs = smem;               // 2 * 512
    float* sBs = smem + 1024;        // 2 * 8192
    float* sG  = smem;               // union: 32 x 512
    float* sH  = smem + 17408;       // 32 x 132
    int*   sIdx = (int*)(smem + 17408 + 32 * 132);

    const int tid = threadIdx.x;
    const int rb  = blockIdx.x * BR;

    if (tid < BR) {
        const int k = rb + tid;
        sIdx[tid] = (k < KK) ? idx[k] : 0;
    }

    const int r0 = (tid >> 6) * 8;   // 0,8,16,24
    const int c0 = (tid & 63) * 8;   // 0..504

    float acc[8][8];
    #pragma unroll
    for (int i = 0; i < 8; i++)
        #pragma unroll
        for (int j = 0; j < 8; j++) acc[i][j] = 0.0f;

    // async-load one chunk into buffer `buf`
    auto loadChunk = [&](int kc, int buf) {
        // A: 512 floats per buffer (32 rows x 16 k), transposed store [kk][r]
        #pragma unroll
        for (int it = 0; it < 2; it++) {
            const int l  = tid + it * 256;       // 0..511
            const int r  = l >> 4;               // 0..31 (16 consecutive threads per row -> coalesced)
            const int kk = l & 15;               // 0..15
            __pipeline_memcpy_async(&sAs[buf * 512 + kk * 32 + r],
                                    &g_A[(size_t)(rb + r) * ZDIM + kc * BK + kk], 4);
        }
        // B: 16 x 512 floats from stacked [W_ih; W_hh]
        const float* Bsrc = (kc < 8) ? (W_ih + (size_t)kc * BK * GDIM)
                                     : (W_hh + (size_t)(kc - 8) * BK * GDIM);
        #pragma unroll
        for (int it = 0; it < 8; it++) {
            const int l  = tid + it * 256;       // float4 index 0..2047
            const int kk = l >> 7;
            const int jj = (l & 127) * 4;
            __pipeline_memcpy_async(&sBs[buf * 8192 + kk * 512 + jj],
                                    Bsrc + kk * GDIM + jj, 16);
        }
    };

    loadChunk(0, 0);
    __pipeline_commit();

    int buf = 0;
    for (int kc = 0; kc < NCH; kc++) {
        if (kc + 1 < NCH) {
            loadChunk(kc + 1, buf ^ 1);
            __pipeline_commit();
            __pipeline_wait_prior(1);
        } else {
            __pipeline_wait_prior(0);
        }
        __syncthreads();

        const int ab = buf * 512;
        const int bb = buf * 8192;
        #pragma unroll
        for (int kk = 0; kk < BK; kk++) {
            const float4 a0 = *reinterpret_cast<const float4*>(&sAs[ab + kk * 32 + r0]);
            const float4 a1 = *reinterpret_cast<const float4*>(&sAs[ab + kk * 32 + r0 + 4]);
            const float4 b0 = *reinterpret_cast<const float4*>(&sBs[bb + kk * 512 + c0]);
            const float4 b1 = *reinterpret_cast<const float4*>(&sBs[bb + kk * 512 + c0 + 4]);
            const float a[8] = {a0.x, a0.y, a0.z, a0.w, a1.x, a1.y, a1.z, a1.w};
            const float b[8] = {b0.x, b0.y, b0.z, b0.w, b1.x, b1.y, b1.z, b1.w};
            #pragma unroll
            for (int i = 0; i < 8; i++)
                #pragma unroll
                for (int j = 0; j < 8; j++)
                    acc[i][j] = fmaf(a[i], b[j], acc[i][j]);
        }
        __syncthreads();   // finished reading buf before it is re-filled / before sG overwrite
        buf ^= 1;
    }

    // add biases, write gates to smem (union region is now free)
    float bs[8];
    #pragma unroll
    for (int j = 0; j < 8; j++) bs[j] = b_ih[c0 + j] + b_hh[c0 + j];
    #pragma unroll
    for (int i = 0; i < 8; i++) {
        float4 v0 = make_float4(acc[i][0] + bs[0], acc[i][1] + bs[1], acc[i][2] + bs[2], acc[i][3] + bs[3]);
        float4 v1 = make_float4(acc[i][4] + bs[4], acc[i][5] + bs[5], acc[i][6] + bs[6], acc[i][7] + bs[7]);
        *reinterpret_cast<float4*>(&sG[(r0 + i) * 512 + c0])     = v0;
        *reinterpret_cast<float4*>(&sG[(r0 + i) * 512 + c0 + 4]) = v1;
    }
    __syncthreads();

    // LSTM elementwise: 32 rows x 128 units
    #pragma unroll
    for (int p = 0; p < 16; p++) {
        const int l = tid + p * 256;        // 0..4095
        const int r = l >> 7;
        const int u = l & 127;
        const int k = rb + r;
        if (k < KK) {
            const float gi = sG[r * 512 + u];
            const float gf = sG[r * 512 + 128 + u];
            const float gg = sG[r * 512 + 256 + u];
            const float go = sG[r * 512 + 384 + u];
            const int   id = sIdx[r];
            const float co = cbuf[(size_t)id * RNN + u];
            const float cn = sigm(gf) * co + sigm(gi) * tanhf(gg);
            const float hn = sigm(go) * tanhf(cn);
            g_sc[(size_t)k * RNN + u] = cn;
            g_sh[(size_t)k * RNN + u] = hn;
            sH[r * 132 + u] = hn;
        }
    }
    __syncthreads();

    // output head: 32 rows x 5 outputs
    if (tid < BR * OUTD) {
        const int r = tid / OUTD;
        const int j = tid % OUTD;
        const int k = rb + r;
        if (k < KK) {
            float s = b_out[j];
            #pragma unroll 8
            for (int u = 0; u < RNN; u++) s += sH[r * 132 + u] * W_out[u * OUTD + j];
            g_so[(size_t)k * OUTD + j] = s;
        }
    }
}

// ---------------- scatter winners back to global state + outputs ----------------
__global__ void scatter_kernel(float* __restrict__ hbuf, float* __restrict__ cbuf,
                               float* __restrict__ outFrame,    // [N, OUTD] for this t
                               const int* __restrict__ idx, int t) {
    const int warp = blockIdx.x * 8 + (threadIdx.x >> 5);
    const int lane = threadIdx.x & 31;
    if (warp >= KK) return;
    const int id = idx[warp];
    if (g_winner[id] != t * KK + warp) return;

    const float4* sh4 = reinterpret_cast<const float4*>(g_sh + (size_t)warp * RNN);
    const float4* sc4 = reinterpret_cast<const float4*>(g_sc + (size_t)warp * RNN);
    reinterpret_cast<float4*>(hbuf + (size_t)id * RNN)[lane] = sh4[lane];
    reinterpret_cast<float4*>(cbuf + (size_t)id * RNN)[lane] = sc4[lane];
    if (lane < OUTD) outFrame[(size_t)id * OUTD + lane] = g_so[(size_t)warp * OUTD + lane];
}

// ---------------- launch ----------------
extern "C" void kernel_launch(void* const* d_in, const int* in_sizes, int n_in,
                              void* d_out, int out_size) {
    const float* input_data = (const float*)d_in[0];
    const float* grids      = (const float*)d_in[1];
    const float* h0         = (const float*)d_in[2];
    const float* c0         = (const float*)d_in[3];
    const int*   aidx       = (const int*)  d_in[4];
    const float* W_in       = (const float*)d_in[5];
    const float* b_in       = (const float*)d_in[6];
    const float* W_obs      = (const float*)d_in[7];
    const float* b_obs      = (const float*)d_in[8];
    const float* W_ih       = (const float*)d_in[9];
    const float* b_ih       = (const float*)d_in[10];
    const float* W_hh       = (const float*)d_in[11];
    const float* b_hh       = (const float*)d_in[12];
    const float* W_out      = (const float*)d_in[13];
    const float* b_out      = (const float*)d_in[14];

    float* out  = (float*)d_out;                       // [T, N, OUTD]
    float* hbuf = out + (size_t)TT * NN * OUTD;        // [N, RNN] == h_fin
    float* cbuf = hbuf + (size_t)NN * RNN;             // [N, RNN] == c_fin

    cudaFuncSetAttribute(gates_kernel, cudaFuncAttributeMaxDynamicSharedMemorySize, SM_BYTES);

    // init output + state (fresh every launch -> graph-replay deterministic)
    cudaMemsetAsync(out, 0, (size_t)TT * NN * OUTD * sizeof(float), 0);
    cudaMemcpyAsync(hbuf, h0, (size_t)NN * RNN * sizeof(float), cudaMemcpyDeviceToDevice, 0);
    cudaMemcpyAsync(cbuf, c0, (size_t)NN * RNN * sizeof(float), cudaMemcpyDeviceToDevice, 0);
    winner_init_kernel<<<(NN + 255) / 256, 256>>>();

    for (int t = 0; t < TT; t++) {
        prep_kernel<<<KK / 16, 256>>>(input_data, grids, hbuf, aidx,
                                      W_in, b_in, W_obs, b_obs, t);
        gates_kernel<<<GB, 256, SM_BYTES>>>(W_ih, W_hh, b_ih, b_hh, W_out, b_out,
                                            cbuf, aidx + (size_t)t * KK);
        scatter_kernel<<<(KK + 7) / 8, 256>>>(hbuf, cbuf,
                                              out + (size_t)t * NN * OUTD,
                                              aidx + (size_t)t * KK, t);
    }
}

// round 11
// speedup vs baseline: 1.0869x; 1.0869x over previous
#include <cuda_runtime.h>
#include <cuda_pipeline.h>
#include <math.h>

// Problem dims
#define TT   20
#define NN   50000
#define KK   10000
#define RNN  128
#define EMB  64
#define INS  2
#define OUTD 5
#define G2   16
#define ZDIM 256            // [ie(64) | te(64) | h(128)]
#define GDIM 512            // 4*RNN

// GEMM tiling
#define BR   32             // rows per block
#define BK   16             // k-chunk
#define NCH  (ZDIM / BK)    // 16 chunks
#define GB   ((KK + BR - 1) / BR)   // 313 blocks
#define KPAD (GB * BR)              // 10016

// ---------------- device scratch (static, zero-initialized) ----------------
__device__ float g_A[(size_t)KPAD * ZDIM];     // activation matrix per frame
__device__ float g_sh[(size_t)KK * RNN];       // staged h_new
__device__ float g_sc[(size_t)KK * RNN];       // staged c_new
__device__ float g_so[(size_t)KK * OUTD];      // staged out
__device__ int   g_winner[NN];                 // last-k-wins tag per node

__device__ __forceinline__ float sigm(float x) { return 1.0f / (1.0f + expf(-x)); }

// packed fp32x2 FMA (Blackwell FFMA2 — only reachable via PTX)
#define FFMA2(d, a, b) \
    asm("fma.rn.f32x2 %0, %1, %2, %0;" : "+l"(d) : "l"(a), "l"(b))

union U64F2 { unsigned long long u; float2 f; };

// ---------------- init winner tags ----------------
__global__ void winner_init_kernel() {
    int i = blockIdx.x * blockDim.x + threadIdx.x;
    if (i < NN) g_winner[i] = -1;
}

// ---------------- prep: build A = [relu(x@W_in+b) | relu(obs@W_obs+b) | h gather] ----------------
__global__ void prep_kernel(const float* __restrict__ input_data,   // [T,N,2]
                            const float* __restrict__ grids,        // [T,K,16]
                            const float* __restrict__ hbuf,         // [N,128]
                            const int*   __restrict__ aidx,         // [T,K]
                            const float* __restrict__ W_in,  const float* __restrict__ b_in,
                            const float* __restrict__ W_obs, const float* __restrict__ b_obs,
                            int t) {
    __shared__ float sWin[2 * EMB];
    __shared__ float sBin[EMB];
    __shared__ float sWobs[G2 * EMB];
    __shared__ float sBobs[EMB];
    const int tid = threadIdx.x;
    if (tid < 128) sWin[tid] = W_in[tid];
    if (tid < 64)  sBin[tid] = b_in[tid];
    for (int i = tid; i < G2 * EMB; i += 256) sWobs[i] = W_obs[i];
    if (tid >= 64 && tid < 128) sBobs[tid - 64] = b_obs[tid - 64];
    __syncthreads();

    const float* frame = input_data + (size_t)t * NN * INS;
    const float* obs   = grids      + (size_t)t * KK * G2;
    const int*   idx   = aidx       + (size_t)t * KK;

    const int base = blockIdx.x * 16;
    for (int r = 0; r < 16; r++) {
        const int k = base + r;
        const int id = idx[k];
        float* Arow = g_A + (size_t)k * ZDIM;
        if (tid == 0) atomicMax(&g_winner[id], t * KK + k);
        if (tid < 64) {
            float v = frame[id * 2] * sWin[tid] + frame[id * 2 + 1] * sWin[64 + tid] + sBin[tid];
            Arow[tid] = fmaxf(v, 0.0f);
        } else if (tid < 128) {
            const int j = tid - 64;
            float s = sBobs[j];
            #pragma unroll
            for (int m = 0; m < 16; m++) s += obs[k * 16 + m] * sWobs[m * 64 + j];
            Arow[tid] = fmaxf(s, 0.0f);
        } else {
            Arow[tid] = hbuf[(size_t)id * RNN + (tid - 128)];
        }
    }
}

// ---------------- gates GEMM (FFMA2) + LSTM elementwise + output head ----------------
// smem layout (floats):
//  [0 .. 2048)                     sAd (2 buf x 16 kk x 64: A duplicated, [kk][2r],[2r+1])
//  [2048 .. 18432)                 sBs (2 buf x 16 x 512)
//  union over [0..16384):          sG  (32 x 512 gates, used after GEMM)
//  [18432 .. 22656)                sH  (32 x 132, padded)
//  [22656 .. 22688)                sIdx (32 ints)
#define SM_FLOATS (18432 + 32 * 132 + 32)
#define SM_BYTES  (SM_FLOATS * 4)

__global__ __launch_bounds__(256, 2)
void gates_kernel(const float* __restrict__ W_ih, const float* __restrict__ W_hh,
                  const float* __restrict__ b_ih, const float* __restrict__ b_hh,
                  const float* __restrict__ W_out, const float* __restrict__ b_out,
                  const float* __restrict__ cbuf,
                  const int*   __restrict__ idx) {
    extern __shared__ float smem[];
    float* sAd = smem;               // 2 * 1024 (duplicated A)
    float* sBs = smem + 2048;        // 2 * 8192
    float* sG  = smem;               // union: 32 x 512
    float* sH  = smem + 18432;       // 32 x 132
    int*   sIdx = (int*)(smem + 18432 + 32 * 132);

    const int tid = threadIdx.x;
    const int rb  = blockIdx.x * BR;

    if (tid < BR) {
        const int k = rb + tid;
        sIdx[tid] = (k < KK) ? idx[k] : 0;
    }

    const int r0 = (tid >> 6) * 8;   // 0,8,16,24 (warp-uniform)
    const int c0 = (tid & 63) * 8;   // 0..504

    unsigned long long acc2[8][4];   // [i][jp] : packed (col c0+2jp, c0+2jp+1)
    #pragma unroll
    for (int i = 0; i < 8; i++)
        #pragma unroll
        for (int jp = 0; jp < 4; jp++) acc2[i][jp] = 0ull;

    // async-load one chunk into buffer `buf`
    auto loadChunk = [&](int kc, int buf) {
        // A: 512 sources, each duplicated to two smem slots -> [kk][2r],[2r+1]
        #pragma unroll
        for (int it = 0; it < 2; it++) {
            const int l  = tid + it * 256;       // 0..511
            const int r  = l >> 4;               // 0..31
            const int kk = l & 15;               // 0..15
            const float* src = &g_A[(size_t)(rb + r) * ZDIM + kc * BK + kk];
            __pipeline_memcpy_async(&sAd[buf * 1024 + kk * 64 + 2 * r],     src, 4);
            __pipeline_memcpy_async(&sAd[buf * 1024 + kk * 64 + 2 * r + 1], src, 4);
        }
        // B: 16 x 512 floats from stacked [W_ih; W_hh]
        const float* Bsrc = (kc < 8) ? (W_ih + (size_t)kc * BK * GDIM)
                                     : (W_hh + (size_t)(kc - 8) * BK * GDIM);
        #pragma unroll
        for (int it = 0; it < 8; it++) {
            const int l  = tid + it * 256;       // float4 index 0..2047
            const int kk = l >> 7;
            const int jj = (l & 127) * 4;
            __pipeline_memcpy_async(&sBs[buf * 8192 + kk * 512 + jj],
                                    Bsrc + kk * GDIM + jj, 16);
        }
    };

    loadChunk(0, 0);
    __pipeline_commit();

    int buf = 0;
    for (int kc = 0; kc < NCH; kc++) {
        if (kc + 1 < NCH) {
            loadChunk(kc + 1, buf ^ 1);
            __pipeline_commit();
            __pipeline_wait_prior(1);
        } else {
            __pipeline_wait_prior(0);
        }
        __syncthreads();

        const int ab = buf * 1024;
        const int bb = buf * 8192;
        #pragma unroll
        for (int kk = 0; kk < BK; kk++) {
            // duplicated A: each 128-bit load yields two (a,a) pairs (broadcast within warp)
            const ulonglong2 av0 = *reinterpret_cast<const ulonglong2*>(&sAd[ab + kk * 64 + 2 * r0]);
            const ulonglong2 av1 = *reinterpret_cast<const ulonglong2*>(&sAd[ab + kk * 64 + 2 * r0 + 4]);
            const ulonglong2 av2 = *reinterpret_cast<const ulonglong2*>(&sAd[ab + kk * 64 + 2 * r0 + 8]);
            const ulonglong2 av3 = *reinterpret_cast<const ulonglong2*>(&sAd[ab + kk * 64 + 2 * r0 + 12]);
            const ulonglong2 bv0 = *reinterpret_cast<const ulonglong2*>(&sBs[bb + kk * 512 + c0]);
            const ulonglong2 bv1 = *reinterpret_cast<const ulonglong2*>(&sBs[bb + kk * 512 + c0 + 4]);
            const unsigned long long a2[8] = {av0.x, av0.y, av1.x, av1.y,
                                              av2.x, av2.y, av3.x, av3.y};
            const unsigned long long b2[4] = {bv0.x, bv0.y, bv1.x, bv1.y};
            #pragma unroll
            for (int i = 0; i < 8; i++) {
                #pragma unroll
                for (int jp = 0; jp < 4; jp++)
                    FFMA2(acc2[i][jp], a2[i], b2[jp]);
            }
        }
        __syncthreads();   // finished reading buf before re-fill / before sG overwrite
        buf ^= 1;
    }

    // add biases, write gates to smem (union region is now free)
    float bs[8];
    #pragma unroll
    for (int j = 0; j < 8; j++) bs[j] = b_ih[c0 + j] + b_hh[c0 + j];
    #pragma unroll
    for (int i = 0; i < 8; i++) {
        U64F2 p0, p1, p2, p3;
        p0.u = acc2[i][0]; p1.u = acc2[i][1]; p2.u = acc2[i][2]; p3.u = acc2[i][3];
        float4 v0 = make_float4(p0.f.x + bs[0], p0.f.y + bs[1], p1.f.x + bs[2], p1.f.y + bs[3]);
        float4 v1 = make_float4(p2.f.x + bs[4], p2.f.y + bs[5], p3.f.x + bs[6], p3.f.y + bs[7]);
        *reinterpret_cast<float4*>(&sG[(r0 + i) * 512 + c0])     = v0;
        *reinterpret_cast<float4*>(&sG[(r0 + i) * 512 + c0 + 4]) = v1;
    }
    __syncthreads();

    // LSTM elementwise: 32 rows x 128 units
    #pragma unroll
    for (int p = 0; p < 16; p++) {
        const int l = tid + p * 256;        // 0..4095
        const int r = l >> 7;
        const int u = l & 127;
        const int k = rb + r;
        if (k < KK) {
            const float gi = sG[r * 512 + u];
            const float gf = sG[r * 512 + 128 + u];
            const float gg = sG[r * 512 + 256 + u];
            const float go = sG[r * 512 + 384 + u];
            const int   id = sIdx[r];
            const float co = cbuf[(size_t)id * RNN + u];
            const float cn = sigm(gf) * co + sigm(gi) * tanhf(gg);
            const float hn = sigm(go) * tanhf(cn);
            g_sc[(size_t)k * RNN + u] = cn;
            g_sh[(size_t)k * RNN + u] = hn;
            sH[r * 132 + u] = hn;
        }
    }
    __syncthreads();

    // output head: 32 rows x 5 outputs
    if (tid < BR * OUTD) {
        const int r = tid / OUTD;
        const int j = tid % OUTD;
        const int k = rb + r;
        if (k < KK) {
            float s = b_out[j];
            #pragma unroll 8
            for (int u = 0; u < RNN; u++) s += sH[r * 132 + u] * W_out[u * OUTD + j];
            g_so[(size_t)k * OUTD + j] = s;
        }
    }
}

// ---------------- scatter winners back to global state + outputs ----------------
__global__ void scatter_kernel(float* __restrict__ hbuf, float* __restrict__ cbuf,
                               float* __restrict__ outFrame,    // [N, OUTD] for this t
                               const int* __restrict__ idx, int t) {
    const int warp = blockIdx.x * 8 + (threadIdx.x >> 5);
    const int lane = threadIdx.x & 31;
    if (warp >= KK) return;
    const int id = idx[warp];
    if (g_winner[id] != t * KK + warp) return;

    const float4* sh4 = reinterpret_cast<const float4*>(g_sh + (size_t)warp * RNN);
    const float4* sc4 = reinterpret_cast<const float4*>(g_sc + (size_t)warp * RNN);
    reinterpret_cast<float4*>(hbuf + (size_t)id * RNN)[lane] = sh4[lane];
    reinterpret_cast<float4*>(cbuf + (size_t)id * RNN)[lane] = sc4[lane];
    if (lane < OUTD) outFrame[(size_t)id * OUTD + lane] = g_so[(size_t)warp * OUTD + lane];
}

// ---------------- launch ----------------
extern "C" void kernel_launch(void* const* d_in, const int* in_sizes, int n_in,
                              void* d_out, int out_size) {
    const float* input_data = (const float*)d_in[0];
    const float* grids      = (const float*)d_in[1];
    const float* h0         = (const float*)d_in[2];
    const float* c0         = (const float*)d_in[3];
    const int*   aidx       = (const int*)  d_in[4];
    const float* W_in       = (const float*)d_in[5];
    const float* b_in       = (const float*)d_in[6];
    const float* W_obs      = (const float*)d_in[7];
    const float* b_obs      = (const float*)d_in[8];
    const float* W_ih       = (const float*)d_in[9];
    const float* b_ih       = (const float*)d_in[10];
    const float* W_hh       = (const float*)d_in[11];
    const float* b_hh       = (const float*)d_in[12];
    const float* W_out      = (const float*)d_in[13];
    const float* b_out      = (const float*)d_in[14];

    float* out  = (float*)d_out;                       // [T, N, OUTD]
    float* hbuf = out + (size_t)TT * NN * OUTD;        // [N, RNN] == h_fin
    float* cbuf = hbuf + (size_t)NN * RNN;             // [N, RNN] == c_fin

    cudaFuncSetAttribute(gates_kernel, cudaFuncAttributeMaxDynamicSharedMemorySize, SM_BYTES);

    // init output + state (fresh every launch -> graph-replay deterministic)
    cudaMemsetAsync(out, 0, (size_t)TT * NN * OUTD * sizeof(float), 0);
    cudaMemcpyAsync(hbuf, h0, (size_t)NN * RNN * sizeof(float), cudaMemcpyDeviceToDevice, 0);
    cudaMemcpyAsync(cbuf, c0, (size_t)NN * RNN * sizeof(float), cudaMemcpyDeviceToDevice, 0);
    winner_init_kernel<<<(NN + 255) / 256, 256>>>();

    for (int t = 0; t < TT; t++) {
        prep_kernel<<<KK / 16, 256>>>(input_data, grids, hbuf, aidx,
                                      W_in, b_in, W_obs, b_obs, t);
        gates_kernel<<<GB, 256, SM_BYTES>>>(W_ih, W_hh, b_ih, b_hh, W_out, b_out,
                                            cbuf, aidx + (size_t)t * KK);
        scatter_kernel<<<(KK + 7) / 8, 256>>>(hbuf, cbuf,
                                              out + (size_t)t * NN * OUTD,
                                              aidx + (size_t)t * KK, t);
    }
}

// round 14
// speedup vs baseline: 2.2495x; 2.0696x over previous
#include <cuda_runtime.h>
#include <cuda_pipeline.h>
#include <cuda_bf16.h>
#include <math.h>
#include <stdint.h>

// Problem dims
#define TT   20
#define NN   50000
#define KK   10000
#define RNN  128
#define EMB  64
#define INS  2
#define OUTD 5
#define G2   16
#define ZDIM 256            // [ie(64) | te(64) | h(128)]
#define GDIM 512            // 4*RNN
#define KSP  768            // split-K stack: [Ah | Ah | Al]

// GEMM tiling
#define MBT  128
#define NBT  128
#define KBT  64
#define GBM  ((KK + MBT - 1) / MBT)   // 79
#define KPAD2 (GBM * MBT)             // 10112
#define NKC  (KSP / KBT)              // 12

// ---------------- device scratch (static, zero-initialized) ----------------
__device__ __nv_bfloat16 g_Acat[(size_t)KPAD2 * KSP];  // [row][768] = [Ah|Ah|Al]
__device__ __nv_bfloat16 g_Wcat[(size_t)GDIM * KSP];   // [n][768]  = [Wh|Wl|Wh] (k-major)
__device__ float g_G[(size_t)KPAD2 * GDIM];            // gates (pre-bias) fp32
__device__ float g_Cg[(size_t)KK * RNN];               // gathered c_old per frame
__device__ int   g_winner[NN];                         // last-k-wins tag

__device__ __forceinline__ float sigm(float x) { return 1.0f / (1.0f + expf(-x)); }

__device__ __forceinline__ uint32_t smem_u32(const void* p) {
    uint32_t a;
    asm("{ .reg .u64 t; cvta.to.shared.u64 t, %1; cvt.u32.u64 %0, t; }" : "=r"(a) : "l"(p));
    return a;
}
#define SWB(b) ((b) ^ (((b) >> 3) & 0x70))

// ---------------- init winner tags ----------------
__global__ void winner_init_kernel() {
    int i = blockIdx.x * blockDim.x + threadIdx.x;
    if (i < NN) g_winner[i] = -1;
}

// ---------------- weight transpose + split-bf16 stack (once per launch) ----------------
__global__ void wsplit_kernel(const float* __restrict__ W_ih, const float* __restrict__ W_hh) {
    int i = blockIdx.x * blockDim.x + threadIdx.x;   // over 512*768
    if (i >= GDIM * KSP) return;
    int n = i / KSP;
    int k = i % KSP;
    int kk = (k < 256) ? k : ((k < 512) ? k - 256 : k - 512);
    float w = (kk < 128) ? W_ih[(size_t)kk * GDIM + n] : W_hh[(size_t)(kk - 128) * GDIM + n];
    __nv_bfloat16 hi = __float2bfloat16(w);
    if (k < 256 || k >= 512) g_Wcat[i] = hi;                                // Wh slots
    else                     g_Wcat[i] = __float2bfloat16(w - __bfloat162float(hi)); // Wl
}

// ---------------- prep: A' = split([relu(x@W_in+b)|relu(obs@W_obs+b)|h]); gather c ----------------
__global__ void prep_kernel(const float* __restrict__ input_data,   // [T,N,2]
                            const float* __restrict__ grids,        // [T,K,16]
                            const float* __restrict__ hbuf,         // [N,128]
                            const float* __restrict__ cbuf,         // [N,128]
                            const int*   __restrict__ aidx,         // [T,K]
                            const float* __restrict__ W_in,  const float* __restrict__ b_in,
                            const float* __restrict__ W_obs, const float* __restrict__ b_obs,
                            int t) {
    __shared__ float sWin[2 * EMB];
    __shared__ float sBin[EMB];
    __shared__ float sWobs[G2 * EMB];
    __shared__ float sBobs[EMB];
    const int tid = threadIdx.x;
    if (tid < 128) sWin[tid] = W_in[tid];
    if (tid < 64)  sBin[tid] = b_in[tid];
    for (int i = tid; i < G2 * EMB; i += 256) sWobs[i] = W_obs[i];
    if (tid >= 64 && tid < 128) sBobs[tid - 64] = b_obs[tid - 64];
    __syncthreads();

    const float* frame = input_data + (size_t)t * NN * INS;
    const float* obs   = grids      + (size_t)t * KK * G2;
    const int*   idx   = aidx       + (size_t)t * KK;

    const int base = blockIdx.x * 16;
    for (int r = 0; r < 16; r++) {
        const int k = base + r;
        const int id = idx[k];
        if (tid == 0) atomicMax(&g_winner[id], t * KK + k);
        float v;
        if (tid < 64) {
            v = fmaxf(frame[id * 2] * sWin[tid] + frame[id * 2 + 1] * sWin[64 + tid] + sBin[tid], 0.0f);
        } else if (tid < 128) {
            const int j = tid - 64;
            float s = sBobs[j];
            #pragma unroll
            for (int m = 0; m < 16; m++) s += obs[k * 16 + m] * sWobs[m * 64 + j];
            v = fmaxf(s, 0.0f);
        } else {
            v = hbuf[(size_t)id * RNN + (tid - 128)];
        }
        __nv_bfloat16 hi = __float2bfloat16(v);
        __nv_bfloat16 lo = __float2bfloat16(v - __bfloat162float(hi));
        __nv_bfloat16* Arow = g_Acat + (size_t)k * KSP;
        Arow[tid]       = hi;
        Arow[256 + tid] = hi;
        Arow[512 + tid] = lo;
        if (tid < 128) g_Cg[(size_t)k * RNN + tid] = cbuf[(size_t)id * RNN + tid];
    }
}

// ---------------- gates GEMM: mma.sync bf16 (legacy HMMA path) ----------------
// smem: [0,16K) A buf0, [16K,32K) A buf1, [32K,48K) B buf0, [48K,64K) B buf1
#define SM_BYTES 65536

__global__ __launch_bounds__(256, 2)
void gemm_kernel() {
    extern __shared__ char sm[];
    const uint32_t sb = smem_u32(sm);
    const int tid  = threadIdx.x;
    const int wid  = tid >> 5;
    const int lane = tid & 31;
    const int rb   = blockIdx.x * MBT;
    const int nb   = blockIdx.y * NBT;
    const int wm   = wid >> 2;           // 0..1
    const int wn   = wid & 3;            // 0..3

    float d[4][4][4];
    #pragma unroll
    for (int mi = 0; mi < 4; mi++)
        #pragma unroll
        for (int ni = 0; ni < 4; ni++)
            #pragma unroll
            for (int j = 0; j < 4; j++) d[mi][ni][j] = 0.0f;

    auto load = [&](int kc, int buf) {
        #pragma unroll
        for (int it = 0; it < 4; it++) {
            const int l = tid + it * 256;       // 0..1023
            const int r = l >> 3;
            const int u = l & 7;
            const uint32_t dsw = SWB((uint32_t)(r * 128 + u * 16));
            __pipeline_memcpy_async(sm + buf * 16384 + dsw,
                (const char*)g_Acat + ((size_t)(rb + r) * KSP + kc * KBT + u * 8) * 2, 16);
            __pipeline_memcpy_async(sm + 32768 + buf * 16384 + dsw,
                (const char*)g_Wcat + ((size_t)(nb + r) * KSP + kc * KBT + u * 8) * 2, 16);
        }
    };

    load(0, 0);
    __pipeline_commit();

    // ldmatrix per-lane addressing
    const int grp   = lane >> 3;
    const int rowA  = (lane & 7) + (grp & 1) * 8;
    const int kOffA = (grp >> 1) * 8;
    const int rowB  = (lane & 7) + (lane >> 4) * 8;
    const int kOffB = ((lane >> 3) & 1) * 8;

    int buf = 0;
    for (int kc = 0; kc < NKC; kc++) {
        if (kc + 1 < NKC) {
            load(kc + 1, buf ^ 1);
            __pipeline_commit();
            __pipeline_wait_prior(1);
        } else {
            __pipeline_wait_prior(0);
        }
        __syncthreads();

        const uint32_t aBase = sb + buf * 16384;
        const uint32_t bBase = sb + 32768 + buf * 16384;
        #pragma unroll
        for (int ks = 0; ks < 4; ks++) {
            uint32_t a[4][4];
            #pragma unroll
            for (int mi = 0; mi < 4; mi++) {
                const uint32_t addr = aBase +
                    SWB((uint32_t)((wm * 64 + mi * 16 + rowA) * 128 + (ks * 16 + kOffA) * 2));
                asm volatile("ldmatrix.sync.aligned.m8n8.x4.shared.b16 {%0,%1,%2,%3}, [%4];"
                    : "=r"(a[mi][0]), "=r"(a[mi][1]), "=r"(a[mi][2]), "=r"(a[mi][3])
                    : "r"(addr));
            }
            uint32_t b[4][2];
            #pragma unroll
            for (int ni2 = 0; ni2 < 2; ni2++) {
                const uint32_t addr = bBase +
                    SWB((uint32_t)((wn * 32 + ni2 * 16 + rowB) * 128 + (ks * 16 + kOffB) * 2));
                uint32_t r0, r1, r2, r3;
                asm volatile("ldmatrix.sync.aligned.m8n8.x4.shared.b16 {%0,%1,%2,%3}, [%4];"
                    : "=r"(r0), "=r"(r1), "=r"(r2), "=r"(r3) : "r"(addr));
                b[ni2 * 2][0] = r0;  b[ni2 * 2][1] = r1;
                b[ni2 * 2 + 1][0] = r2;  b[ni2 * 2 + 1][1] = r3;
            }
            #pragma unroll
            for (int mi = 0; mi < 4; mi++)
                #pragma unroll
                for (int ni = 0; ni < 4; ni++)
                    asm volatile(
                        "mma.sync.aligned.m16n8k16.row.col.f32.bf16.bf16.f32 "
                        "{%0,%1,%2,%3}, {%4,%5,%6,%7}, {%8,%9}, {%0,%1,%2,%3};"
                        : "+f"(d[mi][ni][0]), "+f"(d[mi][ni][1]),
                          "+f"(d[mi][ni][2]), "+f"(d[mi][ni][3])
                        : "r"(a[mi][0]), "r"(a[mi][1]), "r"(a[mi][2]), "r"(a[mi][3]),
                          "r"(b[ni][0]), "r"(b[ni][1]));
        }
        __syncthreads();
        buf ^= 1;
    }

    // store C to global gates buffer
    #pragma unroll
    for (int mi = 0; mi < 4; mi++) {
        const int row = rb + wm * 64 + mi * 16 + (lane >> 2);
        #pragma unroll
        for (int ni = 0; ni < 4; ni++) {
            const int col = nb + wn * 32 + ni * 8 + (lane & 3) * 2;
            *reinterpret_cast<float2*>(&g_G[(size_t)row * GDIM + col]) =
                make_float2(d[mi][ni][0], d[mi][ni][1]);
            *reinterpret_cast<float2*>(&g_G[(size_t)(row + 8) * GDIM + col]) =
                make_float2(d[mi][ni][2], d[mi][ni][3]);
        }
    }
}

// ---------------- fused LSTM + output head + winner scatter (warp per row) ----------------
__global__ void lstm_scatter_kernel(float* __restrict__ hbuf, float* __restrict__ cbuf,
                                    float* __restrict__ outF,
                                    const int* __restrict__ idx,   // frame-offset pointer!
                                    const float* __restrict__ b_ih, const float* __restrict__ b_hh,
                                    const float* __restrict__ W_out, const float* __restrict__ b_out,
                                    int t) {
    const int k    = blockIdx.x * 8 + (threadIdx.x >> 5);
    const int lane = threadIdx.x & 31;
    if (k >= KK) return;
    const int id = idx[k];
    if (g_winner[id] != t * KK + k) return;    // non-winners: all work discarded anyway

    const int u = lane * 4;
    const float* G = g_G + (size_t)k * GDIM;
    const float4 gi = *reinterpret_cast<const float4*>(G + u);
    const float4 gf = *reinterpret_cast<const float4*>(G + 128 + u);
    const float4 gg = *reinterpret_cast<const float4*>(G + 256 + u);
    const float4 go = *reinterpret_cast<const float4*>(G + 384 + u);
    const float4 c4 = *reinterpret_cast<const float4*>(g_Cg + (size_t)k * RNN + u);

    const float vi[4] = {gi.x, gi.y, gi.z, gi.w};
    const float vf[4] = {gf.x, gf.y, gf.z, gf.w};
    const float vg[4] = {gg.x, gg.y, gg.z, gg.w};
    const float vo[4] = {go.x, go.y, go.z, go.w};
    const float cc[4] = {c4.x, c4.y, c4.z, c4.w};
    float cn[4], hn[4];
    #pragma unroll
    for (int j = 0; j < 4; j++) {
        const float bi = b_ih[u + j]       + b_hh[u + j];
        const float bf = b_ih[128 + u + j] + b_hh[128 + u + j];
        const float bg = b_ih[256 + u + j] + b_hh[256 + u + j];
        const float bo = b_ih[384 + u + j] + b_hh[384 + u + j];
        const float c_ = sigm(vf[j] + bf) * cc[j] + sigm(vi[j] + bi) * tanhf(vg[j] + bg);
        const float h_ = sigm(vo[j] + bo) * tanhf(c_);
        cn[j] = c_; hn[j] = h_;
    }
    *reinterpret_cast<float4*>(cbuf + (size_t)id * RNN + u) = make_float4(cn[0], cn[1], cn[2], cn[3]);
    *reinterpret_cast<float4*>(hbuf + (size_t)id * RNN + u) = make_float4(hn[0], hn[1], hn[2], hn[3]);

    // output head: warp reduction over 128 units
    float p[5] = {0.f, 0.f, 0.f, 0.f, 0.f};
    #pragma unroll
    for (int j = 0; j < 4; j++) {
        const float* wr = W_out + (size_t)(u + j) * OUTD;
        #pragma unroll
        for (int o = 0; o < 5; o++) p[o] += hn[j] * wr[o];
    }
    #pragma unroll
    for (int off = 16; off; off >>= 1)
        #pragma unroll
        for (int o = 0; o < 5; o++) p[o] += __shfl_down_sync(0xffffffffu, p[o], off);
    if (lane == 0) {
        #pragma unroll
        for (int o = 0; o < 5; o++) outF[(size_t)id * OUTD + o] = p[o] + b_out[o];
    }
}

// ---------------- launch ----------------
extern "C" void kernel_launch(void* const* d_in, const int* in_sizes, int n_in,
                              void* d_out, int out_size) {
    const float* input_data = (const float*)d_in[0];
    const float* grids      = (const float*)d_in[1];
    const float* h0         = (const float*)d_in[2];
    const float* c0         = (const float*)d_in[3];
    const int*   aidx       = (const int*)  d_in[4];
    const float* W_in       = (const float*)d_in[5];
    const float* b_in       = (const float*)d_in[6];
    const float* W_obs      = (const float*)d_in[7];
    const float* b_obs      = (const float*)d_in[8];
    const float* W_ih       = (const float*)d_in[9];
    const float* b_ih       = (const float*)d_in[10];
    const float* W_hh       = (const float*)d_in[11];
    const float* b_hh       = (const float*)d_in[12];
    const float* W_out      = (const float*)d_in[13];
    const float* b_out      = (const float*)d_in[14];

    float* out  = (float*)d_out;                       // [T, N, OUTD]
    float* hbuf = out + (size_t)TT * NN * OUTD;        // [N, RNN] == h_fin
    float* cbuf = hbuf + (size_t)NN * RNN;             // [N, RNN] == c_fin

    cudaFuncSetAttribute(gemm_kernel, cudaFuncAttributeMaxDynamicSharedMemorySize, SM_BYTES);

    cudaMemsetAsync(out, 0, (size_t)TT * NN * OUTD * sizeof(float), 0);
    cudaMemcpyAsync(hbuf, h0, (size_t)NN * RNN * sizeof(float), cudaMemcpyDeviceToDevice, 0);
    cudaMemcpyAsync(cbuf, c0, (size_t)NN * RNN * sizeof(float), cudaMemcpyDeviceToDevice, 0);
    winner_init_kernel<<<(NN + 255) / 256, 256>>>();
    wsplit_kernel<<<(GDIM * KSP + 255) / 256, 256>>>(W_ih, W_hh);

    for (int t = 0; t < TT; t++) {
        prep_kernel<<<KK / 16, 256>>>(input_data, grids, hbuf, cbuf, aidx,
                                      W_in, b_in, W_obs, b_obs, t);
        gemm_kernel<<<dim3(GBM, 4), 256, SM_BYTES>>>();
        lstm_scatter_kernel<<<(KK + 7) / 8, 256>>>(hbuf, cbuf,
                                                   out + (size_t)t * NN * OUTD,
                                                   aidx + (size_t)t * KK,   // FIX: frame offset
                                                   b_ih, b_hh, W_out, b_out, t);
    }
}

// round 15
// speedup vs baseline: 2.7639x; 1.2287x over previous
#include <cuda_runtime.h>
#include <cuda_pipeline.h>
#include <cuda_bf16.h>
#include <math.h>
#include <stdint.h>

// Problem dims
#define TT   20
#define NN   50000
#define KK   10000
#define RNN  128
#define EMB  64
#define INS  2
#define OUTD 5
#define G2   16
#define ZDIM 256
#define GDIM 512            // 4*RNN
#define KSP  768            // split-K stack: [Ah | Ah | Al]

// GEMM tiling
#define MBT  128
#define NBT  128
#define KBT  64
#define GBM  ((KK + MBT - 1) / MBT)   // 79
#define KPAD2 (GBM * MBT)             // 10112
#define NKC  (KSP / KBT)              // 12

// ---------------- device scratch (static, zero-initialized) ----------------
__device__ __nv_bfloat16 g_Acat[(size_t)TT * KPAD2 * KSP]; // per-frame A' (310 MB)
__device__ __nv_bfloat16 g_Wcat[(size_t)GDIM * KSP];       // [n][768] = [Wh|Wl|Wh]
__device__ float g_G[(size_t)KPAD2 * GDIM];                // gates (pre-bias) fp32
__device__ int   g_W[(size_t)TT * NN];                     // per-frame winner (max k)

__device__ __forceinline__ float sigm(float x) { return 1.0f / (1.0f + expf(-x)); }

__device__ __forceinline__ uint32_t smem_u32(const void* p) {
    uint32_t a;
    asm("{ .reg .u64 t; cvta.to.shared.u64 t, %1; cvt.u32.u64 %0, t; }" : "=r"(a) : "l"(p));
    return a;
}
#define SWB(b) ((b) ^ (((b) >> 3) & 0x70))

// ---------------- winner tags: init + per-frame max-k ----------------
__global__ void wtag_init_kernel() {
    int i = blockIdx.x * blockDim.x + threadIdx.x;
    if (i < TT * NN) g_W[i] = -1;
}
__global__ void wtag_kernel(const int* __restrict__ aidx) {
    int i = blockIdx.x * blockDim.x + threadIdx.x;     // over TT*KK
    if (i >= TT * KK) return;
    int t = i / KK, k = i % KK;
    atomicMax(&g_W[(size_t)t * NN + aidx[i]], k);
}

// ---------------- weight transpose + split-bf16 stack (once) ----------------
__global__ void wsplit_kernel(const float* __restrict__ W_ih, const float* __restrict__ W_hh) {
    int i = blockIdx.x * blockDim.x + threadIdx.x;
    if (i >= GDIM * KSP) return;
    int n = i / KSP;
    int k = i % KSP;
    int kk = (k < 256) ? k : ((k < 512) ? k - 256 : k - 512);
    float w = (kk < 128) ? W_ih[(size_t)kk * GDIM + n] : W_hh[(size_t)(kk - 128) * GDIM + n];
    __nv_bfloat16 hi = __float2bfloat16(w);
    if (k < 256 || k >= 512) g_Wcat[i] = hi;
    else                     g_Wcat[i] = __float2bfloat16(w - __bfloat162float(hi));
}

// ---------------- embed: ie/te for ALL frames (frame-independent) ----------------
__global__ void embed_kernel(const float* __restrict__ input_data,   // [T,N,2]
                             const float* __restrict__ grids,        // [T,K,16]
                             const int*   __restrict__ aidx,         // [T,K]
                             const float* __restrict__ W_in,  const float* __restrict__ b_in,
                             const float* __restrict__ W_obs, const float* __restrict__ b_obs) {
    __shared__ float sWin[2 * EMB];
    __shared__ float sBin[EMB];
    __shared__ float sWobs[G2 * EMB];
    __shared__ float sBobs[EMB];
    const int tid = threadIdx.x;
    if (tid < 128) sWin[tid] = W_in[tid];
    if (tid < 64)  sBin[tid] = b_in[tid];
    for (int i = tid; i < G2 * EMB; i += 256) sWobs[i] = W_obs[i];
    if (tid >= 64 && tid < 128) sBobs[tid - 64] = b_obs[tid - 64];
    __syncthreads();

    const int half = tid >> 7;        // 0/1 : which of the two rows
    const int j    = tid & 127;       // 0..127 : embedding slot
    const int base = blockIdx.x * 16;
    #pragma unroll
    for (int r2 = 0; r2 < 8; r2++) {
        const int gr = base + r2 * 2 + half;   // 0 .. TT*KK-1
        const int t  = gr / KK;
        const int k  = gr - t * KK;
        const int id = aidx[gr];
        float v;
        if (j < 64) {
            const float* fr = input_data + (size_t)t * NN * INS + (size_t)id * 2;
            v = fmaxf(fr[0] * sWin[j] + fr[1] * sWin[64 + j] + sBin[j], 0.0f);
        } else {
            const int jj = j - 64;
            const float* ob = grids + ((size_t)t * KK + k) * G2;
            float s = sBobs[jj];
            #pragma unroll
            for (int m = 0; m < 16; m++) s += ob[m] * sWobs[m * 64 + jj];
            v = fmaxf(s, 0.0f);
        }
        __nv_bfloat16 hi = __float2bfloat16(v);
        __nv_bfloat16 lo = __float2bfloat16(v - __bfloat162float(hi));
        __nv_bfloat16* Arow = g_Acat + ((size_t)t * KPAD2 + k) * KSP;
        Arow[j]       = hi;
        Arow[256 + j] = hi;
        Arow[512 + j] = lo;
    }
}

// ---------------- hprep (per frame): gather h, split, write A h-parts ----------------
__global__ void hprep_kernel(const float* __restrict__ hbuf,
                             const int* __restrict__ idx,   // frame-offset
                             int t) {
    const int tid  = threadIdx.x;
    const int half = tid >> 7;
    const int u    = tid & 127;
    const int base = blockIdx.x * 16;
    #pragma unroll
    for (int r2 = 0; r2 < 8; r2++) {
        const int k  = base + r2 * 2 + half;
        const int id = idx[k];
        const float v = hbuf[(size_t)id * RNN + u];
        __nv_bfloat16 hi = __float2bfloat16(v);
        __nv_bfloat16 lo = __float2bfloat16(v - __bfloat162float(hi));
        __nv_bfloat16* Arow = g_Acat + ((size_t)t * KPAD2 + k) * KSP;
        Arow[128 + u] = hi;
        Arow[384 + u] = hi;
        Arow[640 + u] = lo;
    }
}

// ---------------- gates GEMM: mma.sync bf16, 3-stage cp.async pipeline ----------------
// smem: A stages [0,48K) 3x16KB ; B stages [48K,96K) 3x16KB
#define SM_BYTES 98304

__global__ __launch_bounds__(256, 2)
void gemm_kernel(int t) {
    extern __shared__ char sm[];
    const uint32_t sb = smem_u32(sm);
    const int tid  = threadIdx.x;
    const int wid  = tid >> 5;
    const int lane = tid & 31;
    const int rb   = blockIdx.x * MBT;
    const int nb   = blockIdx.y * NBT;
    const int wm   = wid >> 2;
    const int wn   = wid & 3;
    const __nv_bfloat16* Abase = g_Acat + (size_t)t * KPAD2 * KSP;

    float d[4][4][4];
    #pragma unroll
    for (int mi = 0; mi < 4; mi++)
        #pragma unroll
        for (int ni = 0; ni < 4; ni++)
            #pragma unroll
            for (int j = 0; j < 4; j++) d[mi][ni][j] = 0.0f;

    auto load = [&](int kc, int s) {
        #pragma unroll
        for (int it = 0; it < 4; it++) {
            const int l = tid + it * 256;
            const int r = l >> 3;
            const int u = l & 7;
            const uint32_t dsw = SWB((uint32_t)(r * 128 + u * 16));
            __pipeline_memcpy_async(sm + s * 16384 + dsw,
                (const char*)Abase + ((size_t)(rb + r) * KSP + kc * KBT + u * 8) * 2, 16);
            __pipeline_memcpy_async(sm + 49152 + s * 16384 + dsw,
                (const char*)g_Wcat + ((size_t)(nb + r) * KSP + kc * KBT + u * 8) * 2, 16);
        }
    };

    load(0, 0); __pipeline_commit();
    load(1, 1); __pipeline_commit();

    const int grp   = lane >> 3;
    const int rowA  = (lane & 7) + (grp & 1) * 8;
    const int kOffA = (grp >> 1) * 8;
    const int rowB  = (lane & 7) + (lane >> 4) * 8;
    const int kOffB = ((lane >> 3) & 1) * 8;

    for (int kc = 0; kc < NKC; kc++) {
        if (kc < NKC - 1) __pipeline_wait_prior(1);
        else              __pipeline_wait_prior(0);
        __syncthreads();                  // stage kc visible; compute(kc-1) done by all
        if (kc + 2 < NKC) { load(kc + 2, (kc + 2) % 3); __pipeline_commit(); }

        const int s = kc % 3;
        const uint32_t aBase = sb + s * 16384;
        const uint32_t bBase = sb + 49152 + s * 16384;
        #pragma unroll
        for (int ks = 0; ks < 4; ks++) {
            uint32_t a[4][4];
            #pragma unroll
            for (int mi = 0; mi < 4; mi++) {
                const uint32_t addr = aBase +
                    SWB((uint32_t)((wm * 64 + mi * 16 + rowA) * 128 + (ks * 16 + kOffA) * 2));
                asm volatile("ldmatrix.sync.aligned.m8n8.x4.shared.b16 {%0,%1,%2,%3}, [%4];"
                    : "=r"(a[mi][0]), "=r"(a[mi][1]), "=r"(a[mi][2]), "=r"(a[mi][3])
                    : "r"(addr));
            }
            uint32_t b[4][2];
            #pragma unroll
            for (int ni2 = 0; ni2 < 2; ni2++) {
                const uint32_t addr = bBase +
                    SWB((uint32_t)((wn * 32 + ni2 * 16 + rowB) * 128 + (ks * 16 + kOffB) * 2));
                uint32_t r0, r1, r2, r3;
                asm volatile("ldmatrix.sync.aligned.m8n8.x4.shared.b16 {%0,%1,%2,%3}, [%4];"
                    : "=r"(r0), "=r"(r1), "=r"(r2), "=r"(r3) : "r"(addr));
                b[ni2 * 2][0] = r0;  b[ni2 * 2][1] = r1;
                b[ni2 * 2 + 1][0] = r2;  b[ni2 * 2 + 1][1] = r3;
            }
            #pragma unroll
            for (int mi = 0; mi < 4; mi++)
                #pragma unroll
                for (int ni = 0; ni < 4; ni++)
                    asm volatile(
                        "mma.sync.aligned.m16n8k16.row.col.f32.bf16.bf16.f32 "
                        "{%0,%1,%2,%3}, {%4,%5,%6,%7}, {%8,%9}, {%0,%1,%2,%3};"
                        : "+f"(d[mi][ni][0]), "+f"(d[mi][ni][1]),
                          "+f"(d[mi][ni][2]), "+f"(d[mi][ni][3])
                        : "r"(a[mi][0]), "r"(a[mi][1]), "r"(a[mi][2]), "r"(a[mi][3]),
                          "r"(b[ni][0]), "r"(b[ni][1]));
        }
    }

    #pragma unroll
    for (int mi = 0; mi < 4; mi++) {
        const int row = rb + wm * 64 + mi * 16 + (lane >> 2);
        #pragma unroll
        for (int ni = 0; ni < 4; ni++) {
            const int col = nb + wn * 32 + ni * 8 + (lane & 3) * 2;
            *reinterpret_cast<float2*>(&g_G[(size_t)row * GDIM + col]) =
                make_float2(d[mi][ni][0], d[mi][ni][1]);
            *reinterpret_cast<float2*>(&g_G[(size_t)(row + 8) * GDIM + col]) =
                make_float2(d[mi][ni][2], d[mi][ni][3]);
        }
    }
}

// ---------------- fused LSTM + output head + winner scatter ----------------
__global__ void lstm_scatter_kernel(float* __restrict__ hbuf, float* __restrict__ cbuf,
                                    float* __restrict__ outF,
                                    const int* __restrict__ idx,   // frame-offset
                                    const float* __restrict__ b_ih, const float* __restrict__ b_hh,
                                    const float* __restrict__ W_out, const float* __restrict__ b_out,
                                    int t) {
    const int k    = blockIdx.x * 8 + (threadIdx.x >> 5);
    const int lane = threadIdx.x & 31;
    if (k >= KK) return;
    const int id = idx[k];
    if (g_W[(size_t)t * NN + id] != k) return;   // only winners matter

    const int u = lane * 4;
    const float* G = g_G + (size_t)k * GDIM;
    const float4 gi = *reinterpret_cast<const float4*>(G + u);
    const float4 gf = *reinterpret_cast<const float4*>(G + 128 + u);
    const float4 gg = *reinterpret_cast<const float4*>(G + 256 + u);
    const float4 go = *reinterpret_cast<const float4*>(G + 384 + u);
    const float4 c4 = *reinterpret_cast<const float4*>(cbuf + (size_t)id * RNN + u);

    const float vi[4] = {gi.x, gi.y, gi.z, gi.w};
    const float vf[4] = {gf.x, gf.y, gf.z, gf.w};
    const float vg[4] = {gg.x, gg.y, gg.z, gg.w};
    const float vo[4] = {go.x, go.y, go.z, go.w};
    const float cc[4] = {c4.x, c4.y, c4.z, c4.w};
    float cn[4], hn[4];
    #pragma unroll
    for (int j = 0; j < 4; j++) {
        const float bi = b_ih[u + j]       + b_hh[u + j];
        const float bf = b_ih[128 + u + j] + b_hh[128 + u + j];
        const float bg = b_ih[256 + u + j] + b_hh[256 + u + j];
        const float bo = b_ih[384 + u + j] + b_hh[384 + u + j];
        const float c_ = sigm(vf[j] + bf) * cc[j] + sigm(vi[j] + bi) * tanhf(vg[j] + bg);
        const float h_ = sigm(vo[j] + bo) * tanhf(c_);
        cn[j] = c_; hn[j] = h_;
    }
    *reinterpret_cast<float4*>(cbuf + (size_t)id * RNN + u) = make_float4(cn[0], cn[1], cn[2], cn[3]);
    *reinterpret_cast<float4*>(hbuf + (size_t)id * RNN + u) = make_float4(hn[0], hn[1], hn[2], hn[3]);

    float p[5] = {0.f, 0.f, 0.f, 0.f, 0.f};
    #pragma unroll
    for (int j = 0; j < 4; j++) {
        const float* wr = W_out + (size_t)(u + j) * OUTD;
        #pragma unroll
        for (int o = 0; o < 5; o++) p[o] += hn[j] * wr[o];
    }
    #pragma unroll
    for (int off = 16; off; off >>= 1)
        #pragma unroll
        for (int o = 0; o < 5; o++) p[o] += __shfl_down_sync(0xffffffffu, p[o], off);
    if (lane == 0) {
        #pragma unroll
        for (int o = 0; o < 5; o++) outF[(size_t)id * OUTD + o] = p[o] + b_out[o];
    }
}

// ---------------- launch ----------------
extern "C" void kernel_launch(void* const* d_in, const int* in_sizes, int n_in,
                              void* d_out, int out_size) {
    const float* input_data = (const float*)d_in[0];
    const float* grids      = (const float*)d_in[1];
    const float* h0         = (const float*)d_in[2];
    const float* c0         = (const float*)d_in[3];
    const int*   aidx       = (const int*)  d_in[4];
    const float* W_in       = (const float*)d_in[5];
    const float* b_in       = (const float*)d_in[6];
    const float* W_obs      = (const float*)d_in[7];
    const float* b_obs      = (const float*)d_in[8];
    const float* W_ih       = (const float*)d_in[9];
    const float* b_ih       = (const float*)d_in[10];
    const float* W_hh       = (const float*)d_in[11];
    const float* b_hh       = (const float*)d_in[12];
    const float* W_out      = (const float*)d_in[13];
    const float* b_out      = (const float*)d_in[14];

    float* out  = (float*)d_out;                       // [T, N, OUTD]
    float* hbuf = out + (size_t)TT * NN * OUTD;        // [N, RNN] == h_fin
    float* cbuf = hbuf + (size_t)NN * RNN;             // [N, RNN] == c_fin

    cudaFuncSetAttribute(gemm_kernel, cudaFuncAttributeMaxDynamicSharedMemorySize, SM_BYTES);

    cudaMemsetAsync(out, 0, (size_t)TT * NN * OUTD * sizeof(float), 0);
    cudaMemcpyAsync(hbuf, h0, (size_t)NN * RNN * sizeof(float), cudaMemcpyDeviceToDevice, 0);
    cudaMemcpyAsync(cbuf, c0, (size_t)NN * RNN * sizeof(float), cudaMemcpyDeviceToDevice, 0);

    // frame-independent preprocessing (once per launch)
    wtag_init_kernel<<<(TT * NN + 255) / 256, 256>>>();
    wtag_kernel<<<(TT * KK + 255) / 256, 256>>>(aidx);
    wsplit_kernel<<<(GDIM * KSP + 255) / 256, 256>>>(W_ih, W_hh);
    embed_kernel<<<TT * KK / 16, 256>>>(input_data, grids, aidx,
                                        W_in, b_in, W_obs, b_obs);

    for (int t = 0; t < TT; t++) {
        hprep_kernel<<<KK / 16, 256>>>(hbuf, aidx + (size_t)t * KK, t);
        gemm_kernel<<<dim3(GBM, 4), 256, SM_BYTES>>>(t);
        lstm_scatter_kernel<<<(KK + 7) / 8, 256>>>(hbuf, cbuf,
                                                   out + (size_t)t * NN * OUTD,
                                                   aidx + (size_t)t * KK,
                                                   b_ih, b_hh, W_out, b_out, t);
    }
}

// round 17
// speedup vs baseline: 2.9168x; 1.0553x over previous
#include <cuda_runtime.h>
#include <cuda_pipeline.h>
#include <cuda_bf16.h>
#include <math.h>
#include <stdint.h>

// Problem dims
#define TT   20
#define NN   50000
#define KK   10000
#define RNN  128
#define EMB  64
#define INS  2
#define OUTD 5
#define G2   16
#define GDIM 512            // 4*RNN
#define KSP2 512            // A layout: [Ahi(256) | Alo(256)]

// GEMM tiling
#define MBT  64
#define NBT  128
#define KBT  64
#define NKC  12                         // 3 terms x 4 chunks
#define GBM  (10112 / MBT)              // 158
#define KPAD2 10112

// ---------------- device scratch (static, zero-initialized) ----------------
__device__ __nv_bfloat16 g_Acat[(size_t)TT * KPAD2 * KSP2]; // per-frame A (207 MB)
__device__ __nv_bfloat16 g_Wcat[(size_t)GDIM * KSP2];       // [n][512] = [Whi|Wlo]
__device__ float g_G[(size_t)KPAD2 * GDIM];                 // gates (pre-bias) fp32
__device__ int   g_W[(size_t)TT * NN];                      // per-frame winner (max k)

__device__ __forceinline__ float sigm(float x) { return 1.0f / (1.0f + expf(-x)); }

__device__ __forceinline__ uint32_t smem_u32(const void* p) {
    uint32_t a;
    asm("{ .reg .u64 t; cvta.to.shared.u64 t, %1; cvt.u32.u64 %0, t; }" : "=r"(a) : "l"(p));
    return a;
}
#define SWB(b) ((b) ^ (((b) >> 3) & 0x70))

// ---------------- winner tags ----------------
__global__ void wtag_init_kernel() {
    int i = blockIdx.x * blockDim.x + threadIdx.x;
    if (i < TT * NN) g_W[i] = -1;
}
__global__ void wtag_kernel(const int* __restrict__ aidx) {
    int i = blockIdx.x * blockDim.x + threadIdx.x;
    if (i >= TT * KK) return;
    int t = i / KK, k = i % KK;
    atomicMax(&g_W[(size_t)t * NN + aidx[i]], k);
}

// ---------------- weight transpose + split-bf16 (once) ----------------
__global__ void wsplit_kernel(const float* __restrict__ W_ih, const float* __restrict__ W_hh) {
    int i = blockIdx.x * blockDim.x + threadIdx.x;
    if (i >= GDIM * KSP2) return;
    int n = i / KSP2;
    int k = i % KSP2;
    int kk = k & 255;
    float w = (kk < 128) ? W_ih[(size_t)kk * GDIM + n] : W_hh[(size_t)(kk - 128) * GDIM + n];
    __nv_bfloat16 hi = __float2bfloat16(w);
    if (k < 256) g_Wcat[i] = hi;
    else         g_Wcat[i] = __float2bfloat16(w - __bfloat162float(hi));
}

// ---------------- embed: ie/te for ALL frames (frame-independent) ----------------
__global__ void embed_kernel(const float* __restrict__ input_data,   // [T,N,2]
                             const float* __restrict__ grids,        // [T,K,16]
                             const int*   __restrict__ aidx,         // [T,K]
                             const float* __restrict__ W_in,  const float* __restrict__ b_in,
                             const float* __restrict__ W_obs, const float* __restrict__ b_obs) {
    __shared__ float sWin[2 * EMB];
    __shared__ float sBin[EMB];
    __shared__ float sWobs[G2 * EMB];
    __shared__ float sBobs[EMB];
    const int tid = threadIdx.x;
    if (tid < 128) sWin[tid] = W_in[tid];
    if (tid < 64)  sBin[tid] = b_in[tid];
    for (int i = tid; i < G2 * EMB; i += 256) sWobs[i] = W_obs[i];
    if (tid >= 64 && tid < 128) sBobs[tid - 64] = b_obs[tid - 64];
    __syncthreads();

    const int half = tid >> 7;
    const int j    = tid & 127;
    const int base = blockIdx.x * 16;
    #pragma unroll
    for (int r2 = 0; r2 < 8; r2++) {
        const int gr = base + r2 * 2 + half;   // 0 .. TT*KK-1
        const int t  = gr / KK;
        const int k  = gr - t * KK;
        const int id = aidx[gr];
        float v;
        if (j < 64) {
            const float* fr = input_data + (size_t)t * NN * INS + (size_t)id * 2;
            v = fmaxf(fr[0] * sWin[j] + fr[1] * sWin[64 + j] + sBin[j], 0.0f);
        } else {
            const int jj = j - 64;
            const float* ob = grids + ((size_t)t * KK + k) * G2;
            float s = sBobs[jj];
            #pragma unroll
            for (int m = 0; m < 16; m++) s += ob[m] * sWobs[m * 64 + jj];
            v = fmaxf(s, 0.0f);
        }
        __nv_bfloat16 hi = __float2bfloat16(v);
        __nv_bfloat16 lo = __float2bfloat16(v - __bfloat162float(hi));
        __nv_bfloat16* Arow = g_Acat + ((size_t)t * KPAD2 + k) * KSP2;
        Arow[j]       = hi;
        Arow[256 + j] = lo;
    }
}

// ---------------- hprep (per frame): gather h, split ----------------
__global__ void hprep_kernel(const float* __restrict__ hbuf,
                             const int* __restrict__ idx, int t) {
    const int tid  = threadIdx.x;
    const int half = tid >> 7;
    const int u    = tid & 127;
    const int base = blockIdx.x * 16;
    #pragma unroll
    for (int r2 = 0; r2 < 8; r2++) {
        const int k  = base + r2 * 2 + half;
        const int id = idx[k];
        const float v = hbuf[(size_t)id * RNN + u];
        __nv_bfloat16 hi = __float2bfloat16(v);
        __nv_bfloat16 lo = __float2bfloat16(v - __bfloat162float(hi));
        __nv_bfloat16* Arow = g_Acat + ((size_t)t * KPAD2 + k) * KSP2;
        Arow[128 + u] = hi;
        Arow[384 + u] = lo;
    }
}

// ---------------- gates GEMM: 64x128 tiles, chunk-indirected split-K ----------------
// smem: A stages 3 x 8KB [0,24K) ; B stages 3 x 16KB [24K,72K)
#define SM_BYTES 73728

__global__ __launch_bounds__(128, 2)
void gemm_kernel(int t) {
    extern __shared__ char sm[];
    const uint32_t sb = smem_u32(sm);
    const int tid  = threadIdx.x;
    const int wid  = tid >> 5;
    const int lane = tid & 31;
    const int rb   = blockIdx.x * MBT;
    const int nb   = blockIdx.y * NBT;
    const int wm   = wid >> 1;           // 0..1 (32-row halves)
    const int wn   = wid & 1;            // 0..1 (64-col halves)
    const __nv_bfloat16* Abase = g_Acat + (size_t)t * KPAD2 * KSP2;

    float d[2][8][4];
    #pragma unroll
    for (int mi = 0; mi < 2; mi++)
        #pragma unroll
        for (int ni = 0; ni < 8; ni++)
            #pragma unroll
            for (int j = 0; j < 4; j++) d[mi][ni][j] = 0.0f;

    auto load = [&](int kc, int s) {
        const int ac = (kc < 8) ? (kc & 3) : (kc - 4);   // A chunk: hi,hi,lo
        const int bc = (kc < 8) ? kc : (kc - 8);         // B chunk: hi,lo,hi
        #pragma unroll
        for (int it = 0; it < 4; it++) {                 // A: 512 x 16B units
            const int l = tid + it * 128;
            const int r = l >> 3;
            const int u = l & 7;
            const uint32_t dsw = SWB((uint32_t)(r * 128 + u * 16));
            __pipeline_memcpy_async(sm + s * 8192 + dsw,
                (const char*)Abase + ((size_t)(rb + r) * KSP2 + ac * KBT + u * 8) * 2, 16);
        }
        #pragma unroll
        for (int it = 0; it < 8; it++) {                 // B: 1024 x 16B units
            const int l = tid + it * 128;
            const int n = l >> 3;
            const int u = l & 7;
            const uint32_t dsw = SWB((uint32_t)(n * 128 + u * 16));
            __pipeline_memcpy_async(sm + 24576 + s * 16384 + dsw,
                (const char*)g_Wcat + ((size_t)(nb + n) * KSP2 + bc * KBT + u * 8) * 2, 16);
        }
    };

    load(0, 0); __pipeline_commit();
    load(1, 1); __pipeline_commit();

    const int grp   = lane >> 3;
    const int rowA  = (lane & 7) + (grp & 1) * 8;
    const int kOffA = (grp >> 1) * 8;
    const int rowB  = (lane & 7) + (lane >> 4) * 8;
    const int kOffB = ((lane >> 3) & 1) * 8;

    for (int kc = 0; kc < NKC; kc++) {
        if (kc < NKC - 1) __pipeline_wait_prior(1);
        else              __pipeline_wait_prior(0);
        __syncthreads();
        if (kc + 2 < NKC) { load(kc + 2, (kc + 2) % 3); __pipeline_commit(); }

        const int s = kc % 3;
        const uint32_t aBase = sb + s * 8192;
        const uint32_t bBase = sb + 24576 + s * 16384;
        #pragma unroll
        for (int ks = 0; ks < 4; ks++) {
            uint32_t a[2][4];
            #pragma unroll
            for (int mi = 0; mi < 2; mi++) {
                const uint32_t addr = aBase +
                    SWB((uint32_t)((wm * 32 + mi * 16 + rowA) * 128 + (ks * 16 + kOffA) * 2));
                asm volatile("ldmatrix.sync.aligned.m8n8.x4.shared.b16 {%0,%1,%2,%3}, [%4];"
                    : "=r"(a[mi][0]), "=r"(a[mi][1]), "=r"(a[mi][2]), "=r"(a[mi][3])
                    : "r"(addr));
            }
            uint32_t b[8][2];
            #pragma unroll
            for (int ni2 = 0; ni2 < 4; ni2++) {
                const uint32_t addr = bBase +
                    SWB((uint32_t)((wn * 64 + ni2 * 16 + rowB) * 128 + (ks * 16 + kOffB) * 2));
                uint32_t r0, r1, r2, r3;
                asm volatile("ldmatrix.sync.aligned.m8n8.x4.shared.b16 {%0,%1,%2,%3}, [%4];"
                    : "=r"(r0), "=r"(r1), "=r"(r2), "=r"(r3) : "r"(addr));
                b[ni2 * 2][0] = r0;  b[ni2 * 2][1] = r1;
                b[ni2 * 2 + 1][0] = r2;  b[ni2 * 2 + 1][1] = r3;
            }
            #pragma unroll
            for (int mi = 0; mi < 2; mi++)
                #pragma unroll
                for (int ni = 0; ni < 8; ni++)
                    asm volatile(
                        "mma.sync.aligned.m16n8k16.row.col.f32.bf16.bf16.f32 "
                        "{%0,%1,%2,%3}, {%4,%5,%6,%7}, {%8,%9}, {%0,%1,%2,%3};"
                        : "+f"(d[mi][ni][0]), "+f"(d[mi][ni][1]),
                          "+f"(d[mi][ni][2]), "+f"(d[mi][ni][3])
                        : "r"(a[mi][0]), "r"(a[mi][1]), "r"(a[mi][2]), "r"(a[mi][3]),
                          "r"(b[ni][0]), "r"(b[ni][1]));
        }
    }

    #pragma unroll
    for (int mi = 0; mi < 2; mi++) {
        const int row = rb + wm * 32 + mi * 16 + (lane >> 2);
        #pragma unroll
        for (int ni = 0; ni < 8; ni++) {
            const int col = nb + wn * 64 + ni * 8 + (lane & 3) * 2;
            *reinterpret_cast<float2*>(&g_G[(size_t)row * GDIM + col]) =
                make_float2(d[mi][ni][0], d[mi][ni][1]);
            *reinterpret_cast<float2*>(&g_G[(size_t)(row + 8) * GDIM + col]) =
                make_float2(d[mi][ni][2], d[mi][ni][3]);
        }
    }
}

// ---------------- fused LSTM + output head + winner scatter ----------------
__global__ void lstm_scatter_kernel(float* __restrict__ hbuf, float* __restrict__ cbuf,
                                    float* __restrict__ outF,
                                    const int* __restrict__ idx,
                                    const float* __restrict__ b_ih, const float* __restrict__ b_hh,
                                    const float* __restrict__ W_out, const float* __restrict__ b_out,
                                    int t) {
    const int k    = blockIdx.x * 8 + (threadIdx.x >> 5);
    const int lane = threadIdx.x & 31;
    if (k >= KK) return;
    const int id = idx[k];
    if (g_W[(size_t)t * NN + id] != k) return;

    const int u = lane * 4;
    const float* G = g_G + (size_t)k * GDIM;
    const float4 gi = *reinterpret_cast<const float4*>(G + u);
    const float4 gf = *reinterpret_cast<const float4*>(G + 128 + u);
    const float4 gg = *reinterpret_cast<const float4*>(G + 256 + u);
    const float4 go = *reinterpret_cast<const float4*>(G + 384 + u);
    const float4 c4 = *reinterpret_cast<const float4*>(cbuf + (size_t)id * RNN + u);

    const float vi[4] = {gi.x, gi.y, gi.z, gi.w};
    const float vf[4] = {gf.x, gf.y, gf.z, gf.w};
    const float vg[4] = {gg.x, gg.y, gg.z, gg.w};
    const float vo[4] = {go.x, go.y, go.z, go.w};
    const float cc[4] = {c4.x, c4.y, c4.z, c4.w};
    float cn[4], hn[4];
    #pragma unroll
    for (int j = 0; j < 4; j++) {
        const float bi = b_ih[u + j]       + b_hh[u + j];
        const float bf = b_ih[128 + u + j] + b_hh[128 + u + j];
        const float bg = b_ih[256 + u + j] + b_hh[256 + u + j];
        const float bo = b_ih[384 + u + j] + b_hh[384 + u + j];
        const float c_ = sigm(vf[j] + bf) * cc[j] + sigm(vi[j] + bi) * tanhf(vg[j] + bg);
        const float h_ = sigm(vo[j] + bo) * tanhf(c_);
        cn[j] = c_; hn[j] = h_;
    }
    *reinterpret_cast<float4*>(cbuf + (size_t)id * RNN + u) = make_float4(cn[0], cn[1], cn[2], cn[3]);
    *reinterpret_cast<float4*>(hbuf + (size_t)id * RNN + u) = make_float4(hn[0], hn[1], hn[2], hn[3]);

    float p[5] = {0.f, 0.f, 0.f, 0.f, 0.f};
    #pragma unroll
    for (int j = 0; j < 4; j++) {
        const float* wr = W_out + (size_t)(u + j) * OUTD;
        #pragma unroll
        for (int o = 0; o < 5; o++) p[o] += hn[j] * wr[o];
    }
    #pragma unroll
    for (int off = 16; off; off >>= 1)
        #pragma unroll
        for (int o = 0; o < 5; o++) p[o] += __shfl_down_sync(0xffffffffu, p[o], off);
    if (lane == 0) {
        #pragma unroll
        for (int o = 0; o < 5; o++) outF[(size_t)id * OUTD + o] = p[o] + b_out[o];
    }
}

// ---------------- launch ----------------
extern "C" void kernel_launch(void* const* d_in, const int* in_sizes, int n_in,
                              void* d_out, int out_size) {
    const float* input_data = (const float*)d_in[0];
    const float* grids      = (const float*)d_in[1];
    const float* h0         = (const float*)d_in[2];
    const float* c0         = (const float*)d_in[3];
    const int*   aidx       = (const int*)  d_in[4];
    const float* W_in       = (const float*)d_in[5];
    const float* b_in       = (const float*)d_in[6];
    const float* W_obs      = (const float*)d_in[7];
    const float* b_obs      = (const float*)d_in[8];
    const float* W_ih       = (const float*)d_in[9];
    const float* b_ih       = (const float*)d_in[10];
    const float* W_hh       = (const float*)d_in[11];
    const float* b_hh       = (const float*)d_in[12];
    const float* W_out      = (const float*)d_in[13];
    const float* b_out      = (const float*)d_in[14];

    float* out  = (float*)d_out;                       // [T, N, OUTD]
    float* hbuf = out + (size_t)TT * NN * OUTD;        // [N, RNN] == h_fin
    float* cbuf = hbuf + (size_t)NN * RNN;             // [N, RNN] == c_fin

    cudaFuncSetAttribute(gemm_kernel, cudaFuncAttributeMaxDynamicSharedMemorySize, SM_BYTES);

    cudaMemsetAsync(out, 0, (size_t)TT * NN * OUTD * sizeof(float), 0);
    cudaMemcpyAsync(hbuf, h0, (size_t)NN * RNN * sizeof(float), cudaMemcpyDeviceToDevice, 0);
    cudaMemcpyAsync(cbuf, c0, (size_t)NN * RNN * sizeof(float), cudaMemcpyDeviceToDevice, 0);

    wtag_init_kernel<<<(TT * NN + 255) / 256, 256>>>();
    wtag_kernel<<<(TT * KK + 255) / 256, 256>>>(aidx);
    wsplit_kernel<<<(GDIM * KSP2 + 255) / 256, 256>>>(W_ih, W_hh);
    embed_kernel<<<TT * KK / 16, 256>>>(input_data, grids, aidx,
                                        W_in, b_in, W_obs, b_obs);

    for (int t = 0; t < TT; t++) {
        hprep_kernel<<<KK / 16, 256>>>(hbuf, aidx + (size_t)t * KK, t);
        gemm_kernel<<<dim3(GBM, 4), 128, SM_BYTES>>>(t);
        lstm_scatter_kernel<<<(KK + 7) / 8, 256>>>(hbuf, cbuf,
                                                   out + (size_t)t * NN * OUTD,
                                                   aidx + (size_t)t * KK,
                                                   b_ih, b_hh, W_out, b_out, t);
    }
}